// round 1
// baseline (speedup 1.0000x reference)
#include <cuda_runtime.h>

#define BB   8
#define SQ   2048
#define SKV  1024
#define EMB_ 1024
#define PROJ_ 1024

// ---------------- scratch (allocation-free) ----------------
__device__ float g_q [(size_t)BB * SQ  * PROJ_];   // 64 MB
__device__ float g_sk[(size_t)BB * SKV * PROJ_];   // 32 MB
__device__ float g_sv[(size_t)BB * SKV * PROJ_];
__device__ float g_ek[(size_t)BB * SKV * PROJ_];
__device__ float g_ev[(size_t)BB * SKV * PROJ_];
__device__ float g_s [(size_t)BB * SQ  * SKV ];    // 64 MB (reused by both attentions)

// ---------------- tiled fp32 GEMM ----------------
// C[m,n] = alpha * sum_k A[m,k] * B'[k,n] (+ bias[n])
// TRANS_B=true : B is [N,K] row-major (B'[k,n] = B[n,k])   (NT)
// TRANS_B=false: B is [K,N] row-major                       (NN)
// blockIdx.z batches via strides. All dims multiples of tile sizes.
template <bool TRANS_B>
__launch_bounds__(256, 2)
__global__ void gemm_kernel(const float* __restrict__ A, const float* __restrict__ B,
                            const float* __restrict__ bias, float* __restrict__ C,
                            int K, int lda, int ldb, int ldc, float alpha,
                            long long sA, long long sB, long long sC)
{
    __shared__ __align__(16) float As[16][132];
    __shared__ __align__(16) float Bs[16][132];

    A += (long long)blockIdx.z * sA;
    B += (long long)blockIdx.z * sB;
    C += (long long)blockIdx.z * sC;

    const int m0  = blockIdx.y * 128;
    const int n0  = blockIdx.x * 128;
    const int tid = threadIdx.x;
    const int tm  = tid >> 4;   // 0..15
    const int tn  = tid & 15;   // 0..15

    float acc[8][8];
#pragma unroll
    for (int i = 0; i < 8; i++)
#pragma unroll
        for (int j = 0; j < 8; j++) acc[i][j] = 0.0f;

    for (int k0 = 0; k0 < K; k0 += 16) {
        // --- load A tile: 128 rows x 16 k, transposed into As[k][m]
#pragma unroll
        for (int rep = 0; rep < 2; rep++) {
            int v   = tid + rep * 256;       // 0..511 (float4 index)
            int row = v >> 2;                // 0..127
            int kq  = (v & 3) * 4;
            float4 a = *(const float4*)(A + (long long)(m0 + row) * lda + k0 + kq);
            As[kq + 0][row] = a.x; As[kq + 1][row] = a.y;
            As[kq + 2][row] = a.z; As[kq + 3][row] = a.w;
        }
        if (TRANS_B) {
#pragma unroll
            for (int rep = 0; rep < 2; rep++) {
                int v   = tid + rep * 256;
                int row = v >> 2;            // n index 0..127
                int kq  = (v & 3) * 4;
                float4 b = *(const float4*)(B + (long long)(n0 + row) * ldb + k0 + kq);
                Bs[kq + 0][row] = b.x; Bs[kq + 1][row] = b.y;
                Bs[kq + 2][row] = b.z; Bs[kq + 3][row] = b.w;
            }
        } else {
#pragma unroll
            for (int rep = 0; rep < 2; rep++) {
                int v  = tid + rep * 256;
                int kk = v >> 5;             // 0..15
                int nq = (v & 31) * 4;
                *(float4*)&Bs[kk][nq] =
                    *(const float4*)(B + (long long)(k0 + kk) * ldb + n0 + nq);
            }
        }
        __syncthreads();

#pragma unroll
        for (int kk = 0; kk < 16; kk++) {
            float a[8], b[8];
            *(float4*)&a[0] = *(const float4*)&As[kk][tm * 8];
            *(float4*)&a[4] = *(const float4*)&As[kk][tm * 8 + 4];
            *(float4*)&b[0] = *(const float4*)&Bs[kk][tn * 8];
            *(float4*)&b[4] = *(const float4*)&Bs[kk][tn * 8 + 4];
#pragma unroll
            for (int i = 0; i < 8; i++)
#pragma unroll
                for (int j = 0; j < 8; j++)
                    acc[i][j] += a[i] * b[j];
        }
        __syncthreads();
    }

    // --- epilogue
#pragma unroll
    for (int i = 0; i < 8; i++) {
        int m = m0 + tm * 8 + i;
#pragma unroll
        for (int j = 0; j < 8; j += 4) {
            int n = n0 + tn * 8 + j;
            float4 r;
            r.x = acc[i][j + 0] * alpha;
            r.y = acc[i][j + 1] * alpha;
            r.z = acc[i][j + 2] * alpha;
            r.w = acc[i][j + 3] * alpha;
            if (bias) {
                float4 bv = *(const float4*)(bias + n);
                r.x += bv.x; r.y += bv.y; r.z += bv.z; r.w += bv.w;
            }
            *(float4*)(C + (long long)m * ldc + n) = r;
        }
    }
}

// ---------------- reductions ----------------
__device__ __forceinline__ float block_sum256(float v, float* red) {
#pragma unroll
    for (int o = 16; o; o >>= 1) v += __shfl_xor_sync(0xffffffffu, v, o);
    if ((threadIdx.x & 31) == 0) red[threadIdx.x >> 5] = v;
    __syncthreads();
    float r = red[0];
#pragma unroll
    for (int i = 1; i < 8; i++) r += red[i];
    __syncthreads();
    return r;
}

__device__ __forceinline__ float block_max256(float v, float* red) {
#pragma unroll
    for (int o = 16; o; o >>= 1) v = fmaxf(v, __shfl_xor_sync(0xffffffffu, v, o));
    if ((threadIdx.x & 31) == 0) red[threadIdx.x >> 5] = v;
    __syncthreads();
    float r = red[0];
#pragma unroll
    for (int i = 1; i < 8; i++) r = fmaxf(r, red[i]);
    __syncthreads();
    return r;
}

// ---------------- softmax over rows of length 1024 ----------------
__global__ void softmax_kernel(float* __restrict__ S)
{
    __shared__ float red[8];
    float* row = S + (size_t)blockIdx.x * SKV;
    const int t = threadIdx.x;           // 256 threads, 4 elems each
    float4 v = ((const float4*)row)[t];

    float m = fmaxf(fmaxf(v.x, v.y), fmaxf(v.z, v.w));
    m = block_max256(m, red);

    v.x = __expf(v.x - m); v.y = __expf(v.y - m);
    v.z = __expf(v.z - m); v.w = __expf(v.w - m);

    float s = v.x + v.y + v.z + v.w;
    s = block_sum256(s, red);
    float inv = 1.0f / s;
    v.x *= inv; v.y *= inv; v.z *= inv; v.w *= inv;
    ((float4*)row)[t] = v;
}

// ---------------- residual + layernorm (in place on io) ----------------
__global__ void ln_kernel(const float* __restrict__ obj, float* __restrict__ io,
                          const float* __restrict__ gamma, const float* __restrict__ beta)
{
    __shared__ float red[8];
    const size_t row = blockIdx.x;
    const float4* o4 = (const float4*)(obj + row * EMB_);
    float4*       y4 = (float4*)(io + row * EMB_);
    const int t = threadIdx.x;

    float4 a = o4[t], b = y4[t];
    float4 x = make_float4(a.x + b.x, a.y + b.y, a.z + b.z, a.w + b.w);

    float s = x.x + x.y + x.z + x.w;
    s = block_sum256(s, red);
    const float mu = s * (1.0f / EMB_);

    float dx = x.x - mu, dy = x.y - mu, dz = x.z - mu, dw = x.w - mu;
    float vs = dx * dx + dy * dy + dz * dz + dw * dw;
    vs = block_sum256(vs, red);
    const float rs = rsqrtf(vs * (1.0f / EMB_) + 1e-5f);

    float4 g = ((const float4*)gamma)[t];
    float4 be = ((const float4*)beta)[t];
    float4 y;
    y.x = dx * rs * g.x + be.x;
    y.y = dy * rs * g.y + be.y;
    y.z = dz * rs * g.z + be.z;
    y.w = dw * rs * g.w + be.w;
    y4[t] = y;
}

// ---------------- launch ----------------
extern "C" void kernel_launch(void* const* d_in, const int* in_sizes, int n_in,
                              void* d_out, int out_size)
{
    const float* obj   = (const float*)d_in[0];
    const float* sub   = (const float*)d_in[1];
    const float* scene = (const float*)d_in[2];
    const float* W_q  = (const float*)d_in[3];  const float* b_q  = (const float*)d_in[4];
    const float* W_sk = (const float*)d_in[5];  const float* b_sk = (const float*)d_in[6];
    const float* W_sv = (const float*)d_in[7];  const float* b_sv = (const float*)d_in[8];
    const float* W_ek = (const float*)d_in[9];  const float* b_ek = (const float*)d_in[10];
    const float* W_ev = (const float*)d_in[11]; const float* b_ev = (const float*)d_in[12];
    const float* ln_g = (const float*)d_in[13]; const float* ln_b = (const float*)d_in[14];

    float* out = (float*)d_out;
    float* O1 = out;
    float* O2 = out + (size_t)BB * SQ * PROJ_;

    float *q, *sk, *sv, *ek, *ev, *S;
    cudaGetSymbolAddress((void**)&q,  g_q);
    cudaGetSymbolAddress((void**)&sk, g_sk);
    cudaGetSymbolAddress((void**)&sv, g_sv);
    cudaGetSymbolAddress((void**)&ek, g_ek);
    cudaGetSymbolAddress((void**)&ev, g_ev);
    cudaGetSymbolAddress((void**)&S,  g_s);

    const dim3 blk(256);
    const float scale = 0.03125f;  // 1024^-0.5

    // ---- projections (NT, +bias): M x 1024, K=1024
    gemm_kernel<true><<<dim3(PROJ_ / 128, (BB * SQ)  / 128, 1), blk>>>(
        obj,   W_q,  b_q,  q,  EMB_, EMB_, EMB_, PROJ_, 1.0f, 0, 0, 0);
    gemm_kernel<true><<<dim3(PROJ_ / 128, (BB * SKV) / 128, 1), blk>>>(
        sub,   W_sk, b_sk, sk, EMB_, EMB_, EMB_, PROJ_, 1.0f, 0, 0, 0);
    gemm_kernel<true><<<dim3(PROJ_ / 128, (BB * SKV) / 128, 1), blk>>>(
        sub,   W_sv, b_sv, sv, EMB_, EMB_, EMB_, PROJ_, 1.0f, 0, 0, 0);
    gemm_kernel<true><<<dim3(PROJ_ / 128, (BB * SKV) / 128, 1), blk>>>(
        scene, W_ek, b_ek, ek, EMB_, EMB_, EMB_, PROJ_, 1.0f, 0, 0, 0);
    gemm_kernel<true><<<dim3(PROJ_ / 128, (BB * SKV) / 128, 1), blk>>>(
        scene, W_ev, b_ev, ev, EMB_, EMB_, EMB_, PROJ_, 1.0f, 0, 0, 0);

    // ---- attention 1: S = scale * Q K^T ; softmax ; O1 = S V
    gemm_kernel<true><<<dim3(SKV / 128, SQ / 128, BB), blk>>>(
        q, sk, nullptr, S, PROJ_, PROJ_, PROJ_, SKV, scale,
        (long long)SQ * PROJ_, (long long)SKV * PROJ_, (long long)SQ * SKV);
    softmax_kernel<<<BB * SQ, blk>>>(S);
    gemm_kernel<false><<<dim3(PROJ_ / 128, SQ / 128, BB), blk>>>(
        S, sv, nullptr, O1, SKV, SKV, PROJ_, PROJ_, 1.0f,
        (long long)SQ * SKV, (long long)SKV * PROJ_, (long long)SQ * PROJ_);

    // ---- attention 2 (reuses S scratch)
    gemm_kernel<true><<<dim3(SKV / 128, SQ / 128, BB), blk>>>(
        q, ek, nullptr, S, PROJ_, PROJ_, PROJ_, SKV, scale,
        (long long)SQ * PROJ_, (long long)SKV * PROJ_, (long long)SQ * SKV);
    softmax_kernel<<<BB * SQ, blk>>>(S);
    gemm_kernel<false><<<dim3(PROJ_ / 128, SQ / 128, BB), blk>>>(
        S, ev, nullptr, O2, SKV, SKV, PROJ_, PROJ_, 1.0f,
        (long long)SQ * SKV, (long long)SKV * PROJ_, (long long)SQ * PROJ_);

    // ---- residual + layernorm (in place on d_out)
    ln_kernel<<<BB * SQ, blk>>>(obj, O1, ln_g, ln_b);
    ln_kernel<<<BB * SQ, blk>>>(obj, O2, ln_g, ln_b);
}

// round 5
// speedup vs baseline: 2.7128x; 2.7128x over previous
#include <cuda_runtime.h>
#include <cstdint>

#define BB   8
#define SQ   2048
#define SKV  1024
#define EMB_ 1024
#define PROJ_ 1024

// ---------------- scratch (allocation-free) ----------------
__device__ float g_q  [(size_t)BB * SQ  * PROJ_];   // 64 MB
__device__ float g_sk [(size_t)BB * SKV * PROJ_];
__device__ float g_vt [(size_t)BB * SKV * PROJ_];   // V^T (subject): [b][p][kv]
__device__ float g_ek [(size_t)BB * SKV * PROJ_];
__device__ float g_evt[(size_t)BB * SKV * PROJ_];   // V^T (scene)
__device__ float g_s  [(size_t)BB * SQ  * SKV ];    // scores (reused)

// ---------------- tf32 mma.sync NT GEMM ----------------
// C[m,n] = alpha * sum_k A[m,k]*B[n,k] (+ bias[n]).  A:[M,K] lda, B:[N,K] ldb, row-major.
// CTA tile 128x128, K chunks of 16, double-buffered smem + register prefetch.
// Warp tile 64x32 (warp grid 2m x 4n).
// TRANS_OUT: write C transposed per 1024-row batch: C[(m>>10)*1M + n*1024 + (m&1023)]
#define SPAD 20

__device__ __forceinline__ uint32_t f2tf32(float x) {
    uint32_t r;
    asm("cvt.rna.tf32.f32 %0, %1;" : "=r"(r) : "f"(x));
    return r;
}

template <bool TRANS_OUT>
__global__ void __launch_bounds__(256, 2) mma_gemm(
    const float* __restrict__ A, const float* __restrict__ B,
    const float* __restrict__ bias, float* __restrict__ C,
    int K, int lda, int ldb, int ldc, float alpha,
    long long sA, long long sB, long long sC)
{
    __shared__ __align__(16) uint32_t As[2][128][SPAD];
    __shared__ __align__(16) uint32_t Bs[2][128][SPAD];

    A += (long long)blockIdx.z * sA;
    B += (long long)blockIdx.z * sB;
    C += (long long)blockIdx.z * sC;
    const int m0 = blockIdx.y * 128;
    const int n0 = blockIdx.x * 128;

    const int tid  = threadIdx.x;
    const int lane = tid & 31;
    const int wid  = tid >> 5;
    const int wm   = wid >> 2;          // 0..1 : warp m offset = wm*64
    const int wn   = wid & 3;           // 0..3 : warp n offset = wn*32
    const int g    = lane >> 2;         // 0..7
    const int tg   = lane & 3;          // 0..3

    float acc[4][4][4];
#pragma unroll
    for (int i = 0; i < 4; i++)
#pragma unroll
        for (int j = 0; j < 4; j++)
#pragma unroll
            for (int c = 0; c < 4; c++) acc[i][j][c] = 0.0f;

    const int ldrow = tid >> 2;         // 0..63 (+64 on rep 1)
    const int kq    = (tid & 3) << 2;   // 0,4,8,12

    const float* Aptr = A + (long long)(m0 + ldrow) * lda + kq;
    const float* Bptr = B + (long long)(n0 + ldrow) * ldb + kq;
    const long long a64 = 64ll * lda, b64 = 64ll * ldb;

    const int niter = K >> 4;
    float4 ar[2], br[2];

    // prologue: load chunk 0
#pragma unroll
    for (int rep = 0; rep < 2; rep++) {
        ar[rep] = *(const float4*)(Aptr + rep * a64);
        br[rep] = *(const float4*)(Bptr + rep * b64);
    }
#pragma unroll
    for (int rep = 0; rep < 2; rep++) {
        int row = ldrow + rep * 64;
        *(uint4*)&As[0][row][kq] = make_uint4(f2tf32(ar[rep].x), f2tf32(ar[rep].y),
                                              f2tf32(ar[rep].z), f2tf32(ar[rep].w));
        *(uint4*)&Bs[0][row][kq] = make_uint4(f2tf32(br[rep].x), f2tf32(br[rep].y),
                                              f2tf32(br[rep].z), f2tf32(br[rep].w));
    }
    __syncthreads();

    for (int it = 0; it < niter; it++) {
        const int cur = it & 1;
        // prefetch next chunk to registers (overlaps with MMA below)
        if (it + 1 < niter) {
            const float* Ap = Aptr + (long long)((it + 1) << 4);
            const float* Bp = Bptr + (long long)((it + 1) << 4);
#pragma unroll
            for (int rep = 0; rep < 2; rep++) {
                ar[rep] = *(const float4*)(Ap + rep * a64);
                br[rep] = *(const float4*)(Bp + rep * b64);
            }
        }

        // MMA over current smem buffer
#pragma unroll
        for (int ks = 0; ks < 16; ks += 8) {
            uint32_t af[4][4];
#pragma unroll
            for (int mt = 0; mt < 4; mt++) {
                int m = wm * 64 + mt * 16 + g;
                af[mt][0] = As[cur][m    ][ks + tg];
                af[mt][1] = As[cur][m + 8][ks + tg];
                af[mt][2] = As[cur][m    ][ks + tg + 4];
                af[mt][3] = As[cur][m + 8][ks + tg + 4];
            }
            uint32_t bf[4][2];
#pragma unroll
            for (int nt = 0; nt < 4; nt++) {
                int n = wn * 32 + nt * 8 + g;
                bf[nt][0] = Bs[cur][n][ks + tg];
                bf[nt][1] = Bs[cur][n][ks + tg + 4];
            }
#pragma unroll
            for (int mt = 0; mt < 4; mt++)
#pragma unroll
                for (int nt = 0; nt < 4; nt++) {
                    asm volatile(
                        "mma.sync.aligned.m16n8k8.row.col.f32.tf32.tf32.f32 "
                        "{%0,%1,%2,%3}, {%4,%5,%6,%7}, {%8,%9}, {%0,%1,%2,%3};"
                        : "+f"(acc[mt][nt][0]), "+f"(acc[mt][nt][1]),
                          "+f"(acc[mt][nt][2]), "+f"(acc[mt][nt][3])
                        : "r"(af[mt][0]), "r"(af[mt][1]), "r"(af[mt][2]), "r"(af[mt][3]),
                          "r"(bf[nt][0]), "r"(bf[nt][1]));
                }
        }

        // store prefetched chunk into the other buffer
        if (it + 1 < niter) {
            const int nxt = cur ^ 1;
#pragma unroll
            for (int rep = 0; rep < 2; rep++) {
                int row = ldrow + rep * 64;
                *(uint4*)&As[nxt][row][kq] = make_uint4(f2tf32(ar[rep].x), f2tf32(ar[rep].y),
                                                        f2tf32(ar[rep].z), f2tf32(ar[rep].w));
                *(uint4*)&Bs[nxt][row][kq] = make_uint4(f2tf32(br[rep].x), f2tf32(br[rep].y),
                                                        f2tf32(br[rep].z), f2tf32(br[rep].w));
            }
            __syncthreads();
        }
    }

    // ---------------- epilogue ----------------
#pragma unroll
    for (int mt = 0; mt < 4; mt++) {
        int m = m0 + wm * 64 + mt * 16 + g;
#pragma unroll
        for (int nt = 0; nt < 4; nt++) {
            int n = n0 + wn * 32 + nt * 8 + 2 * tg;
            float bx = 0.f, by = 0.f;
            if (bias) { bx = __ldg(bias + n); by = __ldg(bias + n + 1); }
            float v0 = acc[mt][nt][0] * alpha + bx;
            float v1 = acc[mt][nt][1] * alpha + by;
            float v2 = acc[mt][nt][2] * alpha + bx;
            float v3 = acc[mt][nt][3] * alpha + by;
            if (TRANS_OUT) {
                long long base0 = (long long)(m >> 10) * (1024ll * 1024) + (m & 1023);
                long long base1 = (long long)((m + 8) >> 10) * (1024ll * 1024) + ((m + 8) & 1023);
                C[base0 + (long long)n * 1024]       = v0;
                C[base0 + (long long)(n + 1) * 1024] = v1;
                C[base1 + (long long)n * 1024]       = v2;
                C[base1 + (long long)(n + 1) * 1024] = v3;
            } else {
                *(float2*)(C + (long long)m * ldc + n)       = make_float2(v0, v1);
                *(float2*)(C + (long long)(m + 8) * ldc + n) = make_float2(v2, v3);
            }
        }
    }
}

// ---------------- reductions ----------------
__device__ __forceinline__ float block_sum256(float v, float* red) {
#pragma unroll
    for (int o = 16; o; o >>= 1) v += __shfl_xor_sync(0xffffffffu, v, o);
    if ((threadIdx.x & 31) == 0) red[threadIdx.x >> 5] = v;
    __syncthreads();
    float r = red[0];
#pragma unroll
    for (int i = 1; i < 8; i++) r += red[i];
    __syncthreads();
    return r;
}
__device__ __forceinline__ float block_max256(float v, float* red) {
#pragma unroll
    for (int o = 16; o; o >>= 1) v = fmaxf(v, __shfl_xor_sync(0xffffffffu, v, o));
    if ((threadIdx.x & 31) == 0) red[threadIdx.x >> 5] = v;
    __syncthreads();
    float r = red[0];
#pragma unroll
    for (int i = 1; i < 8; i++) r = fmaxf(r, red[i]);
    __syncthreads();
    return r;
}

// ---------------- softmax over rows of length 1024 ----------------
__global__ void softmax_kernel(float* __restrict__ S)
{
    __shared__ float red[8];
    float* row = S + (size_t)blockIdx.x * SKV;
    const int t = threadIdx.x;
    float4 v = ((const float4*)row)[t];
    float m = fmaxf(fmaxf(v.x, v.y), fmaxf(v.z, v.w));
    m = block_max256(m, red);
    v.x = __expf(v.x - m); v.y = __expf(v.y - m);
    v.z = __expf(v.z - m); v.w = __expf(v.w - m);
    float s = v.x + v.y + v.z + v.w;
    s = block_sum256(s, red);
    float inv = 1.0f / s;
    v.x *= inv; v.y *= inv; v.z *= inv; v.w *= inv;
    ((float4*)row)[t] = v;
}

// ---------------- residual + layernorm (in place) ----------------
__global__ void ln_kernel(const float* __restrict__ obj, float* __restrict__ io,
                          const float* __restrict__ gamma, const float* __restrict__ beta)
{
    __shared__ float red[8];
    const size_t row = blockIdx.x;
    const float4* o4 = (const float4*)(obj + row * EMB_);
    float4*       y4 = (float4*)(io + row * EMB_);
    const int t = threadIdx.x;
    float4 a = o4[t], b = y4[t];
    float4 x = make_float4(a.x + b.x, a.y + b.y, a.z + b.z, a.w + b.w);
    float s = x.x + x.y + x.z + x.w;
    s = block_sum256(s, red);
    const float mu = s * (1.0f / EMB_);
    float dx = x.x - mu, dy = x.y - mu, dz = x.z - mu, dw = x.w - mu;
    float vs = dx * dx + dy * dy + dz * dz + dw * dw;
    vs = block_sum256(vs, red);
    const float rs = rsqrtf(vs * (1.0f / EMB_) + 1e-5f);
    float4 gm = ((const float4*)gamma)[t];
    float4 be = ((const float4*)beta)[t];
    float4 y;
    y.x = dx * rs * gm.x + be.x;
    y.y = dy * rs * gm.y + be.y;
    y.z = dz * rs * gm.z + be.z;
    y.w = dw * rs * gm.w + be.w;
    y4[t] = y;
}

// ---------------- launch ----------------
extern "C" void kernel_launch(void* const* d_in, const int* in_sizes, int n_in,
                              void* d_out, int out_size)
{
    const float* obj   = (const float*)d_in[0];
    const float* sub   = (const float*)d_in[1];
    const float* scene = (const float*)d_in[2];
    const float* W_q  = (const float*)d_in[3];  const float* b_q  = (const float*)d_in[4];
    const float* W_sk = (const float*)d_in[5];  const float* b_sk = (const float*)d_in[6];
    const float* W_sv = (const float*)d_in[7];  const float* b_sv = (const float*)d_in[8];
    const float* W_ek = (const float*)d_in[9];  const float* b_ek = (const float*)d_in[10];
    const float* W_ev = (const float*)d_in[11]; const float* b_ev = (const float*)d_in[12];
    const float* ln_g = (const float*)d_in[13]; const float* ln_b = (const float*)d_in[14];

    float* out = (float*)d_out;
    float* O1 = out;
    float* O2 = out + (size_t)BB * SQ * PROJ_;

    float *q, *sk, *vt, *ek, *evt, *S;
    cudaGetSymbolAddress((void**)&q,   g_q);
    cudaGetSymbolAddress((void**)&sk,  g_sk);
    cudaGetSymbolAddress((void**)&vt,  g_vt);
    cudaGetSymbolAddress((void**)&ek,  g_ek);
    cudaGetSymbolAddress((void**)&evt, g_evt);
    cudaGetSymbolAddress((void**)&S,   g_s);

    const dim3 blk(256);
    const float scale = 0.03125f;  // 1024^-0.5
    const long long ZP = (long long)SQ * PROJ_;
    const long long ZS = (long long)SQ * SKV;
    const long long ZV = (long long)SKV * PROJ_;

    // ---- projections (NT, +bias)
    mma_gemm<false><<<dim3(8, 128, 1), blk>>>(obj,   W_q,  b_q,  q,   EMB_, EMB_, EMB_, PROJ_, 1.0f, 0, 0, 0);
    mma_gemm<false><<<dim3(8,  64, 1), blk>>>(sub,   W_sk, b_sk, sk,  EMB_, EMB_, EMB_, PROJ_, 1.0f, 0, 0, 0);
    mma_gemm<true ><<<dim3(8,  64, 1), blk>>>(sub,   W_sv, b_sv, vt,  EMB_, EMB_, EMB_, PROJ_, 1.0f, 0, 0, 0);
    mma_gemm<false><<<dim3(8,  64, 1), blk>>>(scene, W_ek, b_ek, ek,  EMB_, EMB_, EMB_, PROJ_, 1.0f, 0, 0, 0);
    mma_gemm<true ><<<dim3(8,  64, 1), blk>>>(scene, W_ev, b_ev, evt, EMB_, EMB_, EMB_, PROJ_, 1.0f, 0, 0, 0);

    // ---- attention 1: S = scale*Q K^T ; softmax ; O1 = S V  (V^T is NT operand)
    mma_gemm<false><<<dim3(8, 16, BB), blk>>>(q, sk, nullptr, S, PROJ_, PROJ_, PROJ_, SKV, scale, ZP, ZV, ZS);
    softmax_kernel<<<BB * SQ, blk>>>(S);
    mma_gemm<false><<<dim3(8, 16, BB), blk>>>(S, vt, nullptr, O1, SKV, SKV, SKV, PROJ_, 1.0f, ZS, ZV, ZP);

    // ---- attention 2
    mma_gemm<false><<<dim3(8, 16, BB), blk>>>(q, ek, nullptr, S, PROJ_, PROJ_, PROJ_, SKV, scale, ZP, ZV, ZS);
    softmax_kernel<<<BB * SQ, blk>>>(S);
    mma_gemm<false><<<dim3(8, 16, BB), blk>>>(S, evt, nullptr, O2, SKV, SKV, SKV, PROJ_, 1.0f, ZS, ZV, ZP);

    // ---- residual + layernorm
    ln_kernel<<<BB * SQ, blk>>>(obj, O1, ln_g, ln_b);
    ln_kernel<<<BB * SQ, blk>>>(obj, O2, ln_g, ln_b);
}

// round 6
// speedup vs baseline: 3.5559x; 1.3108x over previous
#include <cuda_runtime.h>
#include <cstdint>

#define BB   8
#define SQ   2048
#define SKV  1024
#define EMB_ 1024
#define PROJ_ 1024

#define SPAD 20
#define NST  3
#define STAGE_W (128 * SPAD)            // words per tile stage
#define STAGE_B (STAGE_W * 4)           // 10240 bytes
#define SMEM_SZ (NST * STAGE_B * 2)     // 61440 bytes

// ---------------- scratch (allocation-free) ----------------
__device__ float g_q  [(size_t)BB * SQ  * PROJ_];   // 64 MB
__device__ float g_sk [(size_t)BB * SKV * PROJ_];
__device__ float g_vt [(size_t)BB * SKV * PROJ_];   // V^T (subject): [b][p][kv]
__device__ float g_ek [(size_t)BB * SKV * PROJ_];
__device__ float g_evt[(size_t)BB * SKV * PROJ_];   // V^T (scene)
__device__ float g_s  [(size_t)BB * SQ  * SKV ];    // scores (reused)
// tf32-rounded copies of GEMM inputs
__device__ float g_or [(size_t)BB * SQ  * EMB_];
__device__ float g_sr [(size_t)BB * SKV * EMB_];
__device__ float g_cr [(size_t)BB * SKV * EMB_];
__device__ float g_w  [5][(size_t)PROJ_ * EMB_];

__device__ __forceinline__ uint32_t f2tf32(float x) {
    uint32_t r;
    asm("cvt.rna.tf32.f32 %0, %1;" : "=r"(r) : "f"(x));
    return r;
}
__device__ __forceinline__ uint32_t smem_u32(const void* p) {
    uint32_t a;
    asm("{ .reg .u64 t; cvta.to.shared.u64 t, %1; cvt.u32.u64 %0, t; }" : "=r"(a) : "l"(p));
    return a;
}

#define CPA(dst, src) asm volatile("cp.async.cg.shared.global [%0], [%1], 16;" :: "r"(dst), "l"(src))
#define CPC()         asm volatile("cp.async.commit_group;" ::: "memory")
#define CPW(n)        asm volatile("cp.async.wait_group %0;" :: "n"(n) : "memory")
#define LDSM4(r0,r1,r2,r3,a) asm volatile("ldmatrix.sync.aligned.m8n8.x4.shared.b16 {%0,%1,%2,%3}, [%4];" \
    : "=r"(r0),"=r"(r1),"=r"(r2),"=r"(r3) : "r"(a))
#define LDSM2(r0,r1,a) asm volatile("ldmatrix.sync.aligned.m8n8.x2.shared.b16 {%0,%1}, [%2];" \
    : "=r"(r0),"=r"(r1) : "r"(a))

// ---------------- pre-round inputs to tf32 ----------------
__global__ void round_kernel(const float* __restrict__ in, float* __restrict__ out, int n4)
{
    int i = blockIdx.x * blockDim.x + threadIdx.x;
    if (i >= n4) return;
    float4 v = ((const float4*)in)[i];
    uint4 u = make_uint4(f2tf32(v.x), f2tf32(v.y), f2tf32(v.z), f2tf32(v.w));
    ((uint4*)out)[i] = u;
}

// ---------------- tf32 mma.sync NT GEMM ----------------
// C[m,n] = alpha * sum_k A[m,k]*B[n,k] (+bias[n]).  A:[M,K], B:[N,K] row-major,
// values already tf32-rounded. CTA 128x128, 4 warps, warp tile 64x64, k-chunk 16,
// 3-stage cp.async pipeline, ldmatrix fragment loads.
// TRANS_OUT: write C^T per 1024-row batch.  cvt_out: round outputs to tf32.
template <bool TRANS_OUT>
__global__ void __launch_bounds__(128, 2) mma_gemm(
    const float* __restrict__ A, const float* __restrict__ B,
    const float* __restrict__ bias, float* __restrict__ C,
    int K, int lda, int ldb, int ldc, float alpha, int cvt_out,
    long long sA, long long sB, long long sC)
{
    extern __shared__ __align__(16) uint32_t sm[];
    const uint32_t sA_base = smem_u32(sm);
    const uint32_t sB_base = sA_base + NST * STAGE_B;

    A += (long long)blockIdx.z * sA;
    B += (long long)blockIdx.z * sB;
    C += (long long)blockIdx.z * sC;
    const int m0 = blockIdx.y * 128;
    const int n0 = blockIdx.x * 128;

    const int tid  = threadIdx.x;
    const int lane = tid & 31;
    const int wid  = tid >> 5;          // 0..3
    const int wm   = wid >> 1;          // warp m offset = wm*64
    const int wn   = wid & 1;           // warp n offset = wn*64
    const int g    = lane >> 2;
    const int tg   = lane & 3;

    // ldmatrix lane-address offsets (bytes)
    const int r8  = lane & 7, sel = lane >> 3;
    const uint32_t aoff = (uint32_t)(((r8 + ((sel & 1) << 3)) * SPAD + ((sel >> 1) << 2)) << 2);
    const uint32_t boff = (uint32_t)((r8 * SPAD + ((sel & 1) << 2)) << 2);

    // loader mapping: thread -> (row = tid>>2 + i*32, kq = (tid&3)*4), i = 0..3
    const int lrow = tid >> 2;
    const int lkq  = (tid & 3) << 2;
    const float* Ap = A + (long long)(m0 + lrow) * lda + lkq;
    const float* Bp = B + (long long)(n0 + lrow) * ldb + lkq;
    const uint32_t dA = sA_base + (uint32_t)((lrow * SPAD + lkq) << 2);
    const uint32_t dB = sB_base + (uint32_t)((lrow * SPAD + lkq) << 2);
    const long long a32 = 32ll * lda, b32 = 32ll * ldb;

    float acc[4][8][4];
#pragma unroll
    for (int i = 0; i < 4; i++)
#pragma unroll
        for (int j = 0; j < 8; j++)
#pragma unroll
            for (int c = 0; c < 4; c++) acc[i][j][c] = 0.0f;

    const int niter = K >> 4;

    // prologue: issue stages 0..NST-2
#pragma unroll
    for (int s = 0; s < NST - 1; s++) {
        const float* Aps = Ap + (s << 4);
        const float* Bps = Bp + (s << 4);
        const uint32_t da = dA + s * STAGE_B;
        const uint32_t db = dB + s * STAGE_B;
#pragma unroll
        for (int i = 0; i < 4; i++) CPA(da + i * (32 * SPAD * 4), Aps + i * a32);
#pragma unroll
        for (int i = 0; i < 4; i++) CPA(db + i * (32 * SPAD * 4), Bps + i * b32);
        CPC();
    }

    for (int it = 0; it < niter; it++) {
        const int cur = it % NST;
        CPW(NST - 2);
        __syncthreads();

        const int nit = it + NST - 1;
        if (nit < niter) {
            const int s = nit % NST;
            const float* Aps = Ap + (nit << 4);
            const float* Bps = Bp + (nit << 4);
            const uint32_t da = dA + s * STAGE_B;
            const uint32_t db = dB + s * STAGE_B;
#pragma unroll
            for (int i = 0; i < 4; i++) CPA(da + i * (32 * SPAD * 4), Aps + i * a32);
#pragma unroll
            for (int i = 0; i < 4; i++) CPA(db + i * (32 * SPAD * 4), Bps + i * b32);
            CPC();
        }

        const uint32_t sa = sA_base + cur * STAGE_B;
        const uint32_t sb = sB_base + cur * STAGE_B;
#pragma unroll
        for (int ksi = 0; ksi < 2; ksi++) {
            const int ks = ksi << 3;
            uint32_t af[4][4];
#pragma unroll
            for (int mt = 0; mt < 4; mt++) {
                uint32_t ad = sa + (uint32_t)((((wm * 64 + mt * 16) * SPAD + ks) << 2)) + aoff;
                LDSM4(af[mt][0], af[mt][1], af[mt][2], af[mt][3], ad);
            }
            uint32_t bf[8][2];
#pragma unroll
            for (int nt = 0; nt < 8; nt++) {
                uint32_t bd = sb + (uint32_t)((((wn * 64 + nt * 8) * SPAD + ks) << 2)) + boff;
                LDSM2(bf[nt][0], bf[nt][1], bd);
            }
#pragma unroll
            for (int mt = 0; mt < 4; mt++)
#pragma unroll
                for (int nt = 0; nt < 8; nt++) {
                    asm volatile(
                        "mma.sync.aligned.m16n8k8.row.col.f32.tf32.tf32.f32 "
                        "{%0,%1,%2,%3}, {%4,%5,%6,%7}, {%8,%9}, {%0,%1,%2,%3};"
                        : "+f"(acc[mt][nt][0]), "+f"(acc[mt][nt][1]),
                          "+f"(acc[mt][nt][2]), "+f"(acc[mt][nt][3])
                        : "r"(af[mt][0]), "r"(af[mt][1]), "r"(af[mt][2]), "r"(af[mt][3]),
                          "r"(bf[nt][0]), "r"(bf[nt][1]));
                }
        }
    }

    // ---------------- epilogue ----------------
#pragma unroll
    for (int mt = 0; mt < 4; mt++) {
        int m = m0 + wm * 64 + mt * 16 + g;
#pragma unroll
        for (int nt = 0; nt < 8; nt++) {
            int n = n0 + wn * 64 + nt * 8 + 2 * tg;
            float bx = 0.f, by = 0.f;
            if (bias) { bx = __ldg(bias + n); by = __ldg(bias + n + 1); }
            float v0 = acc[mt][nt][0] * alpha + bx;
            float v1 = acc[mt][nt][1] * alpha + by;
            float v2 = acc[mt][nt][2] * alpha + bx;
            float v3 = acc[mt][nt][3] * alpha + by;
            if (cvt_out) {
                v0 = __uint_as_float(f2tf32(v0));
                v1 = __uint_as_float(f2tf32(v1));
                v2 = __uint_as_float(f2tf32(v2));
                v3 = __uint_as_float(f2tf32(v3));
            }
            if (TRANS_OUT) {
                long long base0 = (long long)(m >> 10) * (1024ll * 1024) + (m & 1023);
                long long base1 = (long long)((m + 8) >> 10) * (1024ll * 1024) + ((m + 8) & 1023);
                C[base0 + (long long)n * 1024]       = v0;
                C[base0 + (long long)(n + 1) * 1024] = v1;
                C[base1 + (long long)n * 1024]       = v2;
                C[base1 + (long long)(n + 1) * 1024] = v3;
            } else {
                *(float2*)(C + (long long)m * ldc + n)       = make_float2(v0, v1);
                *(float2*)(C + (long long)(m + 8) * ldc + n) = make_float2(v2, v3);
            }
        }
    }
}

// ---------------- reductions ----------------
__device__ __forceinline__ float block_sum256(float v, float* red) {
#pragma unroll
    for (int o = 16; o; o >>= 1) v += __shfl_xor_sync(0xffffffffu, v, o);
    if ((threadIdx.x & 31) == 0) red[threadIdx.x >> 5] = v;
    __syncthreads();
    float r = red[0];
#pragma unroll
    for (int i = 1; i < 8; i++) r += red[i];
    __syncthreads();
    return r;
}
__device__ __forceinline__ float block_max256(float v, float* red) {
#pragma unroll
    for (int o = 16; o; o >>= 1) v = fmaxf(v, __shfl_xor_sync(0xffffffffu, v, o));
    if ((threadIdx.x & 31) == 0) red[threadIdx.x >> 5] = v;
    __syncthreads();
    float r = red[0];
#pragma unroll
    for (int i = 1; i < 8; i++) r = fmaxf(r, red[i]);
    __syncthreads();
    return r;
}

// ---------------- softmax over rows of length 1024 (stores tf32-rounded) ----------------
__global__ void softmax_kernel(float* __restrict__ S)
{
    __shared__ float red[8];
    float* row = S + (size_t)blockIdx.x * SKV;
    const int t = threadIdx.x;
    float4 v = ((const float4*)row)[t];
    float m = fmaxf(fmaxf(v.x, v.y), fmaxf(v.z, v.w));
    m = block_max256(m, red);
    v.x = __expf(v.x - m); v.y = __expf(v.y - m);
    v.z = __expf(v.z - m); v.w = __expf(v.w - m);
    float s = v.x + v.y + v.z + v.w;
    s = block_sum256(s, red);
    float inv = 1.0f / s;
    uint4 u = make_uint4(f2tf32(v.x * inv), f2tf32(v.y * inv),
                         f2tf32(v.z * inv), f2tf32(v.w * inv));
    ((uint4*)row)[t] = u;
}

// ---------------- residual + layernorm (in place) ----------------
__global__ void ln_kernel(const float* __restrict__ obj, float* __restrict__ io,
                          const float* __restrict__ gamma, const float* __restrict__ beta)
{
    __shared__ float red[8];
    const size_t row = blockIdx.x;
    const float4* o4 = (const float4*)(obj + row * EMB_);
    float4*       y4 = (float4*)(io + row * EMB_);
    const int t = threadIdx.x;
    float4 a = o4[t], b = y4[t];
    float4 x = make_float4(a.x + b.x, a.y + b.y, a.z + b.z, a.w + b.w);
    float s = x.x + x.y + x.z + x.w;
    s = block_sum256(s, red);
    const float mu = s * (1.0f / EMB_);
    float dx = x.x - mu, dy = x.y - mu, dz = x.z - mu, dw = x.w - mu;
    float vs = dx * dx + dy * dy + dz * dz + dw * dw;
    vs = block_sum256(vs, red);
    const float rs = rsqrtf(vs * (1.0f / EMB_) + 1e-5f);
    float4 gm = ((const float4*)gamma)[t];
    float4 be = ((const float4*)beta)[t];
    float4 y;
    y.x = dx * rs * gm.x + be.x;
    y.y = dy * rs * gm.y + be.y;
    y.z = dz * rs * gm.z + be.z;
    y.w = dw * rs * gm.w + be.w;
    y4[t] = y;
}

// ---------------- launch ----------------
extern "C" void kernel_launch(void* const* d_in, const int* in_sizes, int n_in,
                              void* d_out, int out_size)
{
    const float* obj   = (const float*)d_in[0];
    const float* sub   = (const float*)d_in[1];
    const float* scene = (const float*)d_in[2];
    const float* W_q  = (const float*)d_in[3];  const float* b_q  = (const float*)d_in[4];
    const float* W_sk = (const float*)d_in[5];  const float* b_sk = (const float*)d_in[6];
    const float* W_sv = (const float*)d_in[7];  const float* b_sv = (const float*)d_in[8];
    const float* W_ek = (const float*)d_in[9];  const float* b_ek = (const float*)d_in[10];
    const float* W_ev = (const float*)d_in[11]; const float* b_ev = (const float*)d_in[12];
    const float* ln_g = (const float*)d_in[13]; const float* ln_b = (const float*)d_in[14];

    float* out = (float*)d_out;
    float* O1 = out;
    float* O2 = out + (size_t)BB * SQ * PROJ_;

    float *q, *sk, *vt, *ek, *evt, *S, *orr, *srr, *crr, *wr;
    cudaGetSymbolAddress((void**)&q,   g_q);
    cudaGetSymbolAddress((void**)&sk,  g_sk);
    cudaGetSymbolAddress((void**)&vt,  g_vt);
    cudaGetSymbolAddress((void**)&ek,  g_ek);
    cudaGetSymbolAddress((void**)&evt, g_evt);
    cudaGetSymbolAddress((void**)&S,   g_s);
    cudaGetSymbolAddress((void**)&orr, g_or);
    cudaGetSymbolAddress((void**)&srr, g_sr);
    cudaGetSymbolAddress((void**)&crr, g_cr);
    cudaGetSymbolAddress((void**)&wr,  g_w);

    cudaFuncSetAttribute(mma_gemm<false>, cudaFuncAttributeMaxDynamicSharedMemorySize, SMEM_SZ);
    cudaFuncSetAttribute(mma_gemm<true>,  cudaFuncAttributeMaxDynamicSharedMemorySize, SMEM_SZ);

    const dim3 blk(128);
    const float scale = 0.03125f;  // 1024^-0.5
    const long long ZP = (long long)SQ * PROJ_;
    const long long ZS = (long long)SQ * SKV;
    const long long ZV = (long long)SKV * PROJ_;
    const size_t WSZ = (size_t)PROJ_ * EMB_;

    // ---- pre-round all GEMM inputs to tf32 (rna)
    round_kernel<<<(BB * SQ  * EMB_ / 4 + 255) / 256, 256>>>(obj,   orr, BB * SQ  * EMB_ / 4);
    round_kernel<<<(BB * SKV * EMB_ / 4 + 255) / 256, 256>>>(sub,   srr, BB * SKV * EMB_ / 4);
    round_kernel<<<(BB * SKV * EMB_ / 4 + 255) / 256, 256>>>(scene, crr, BB * SKV * EMB_ / 4);
    round_kernel<<<(int)(WSZ / 4 + 255) / 256, 256>>>(W_q,  wr + 0 * WSZ, (int)(WSZ / 4));
    round_kernel<<<(int)(WSZ / 4 + 255) / 256, 256>>>(W_sk, wr + 1 * WSZ, (int)(WSZ / 4));
    round_kernel<<<(int)(WSZ / 4 + 255) / 256, 256>>>(W_sv, wr + 2 * WSZ, (int)(WSZ / 4));
    round_kernel<<<(int)(WSZ / 4 + 255) / 256, 256>>>(W_ek, wr + 3 * WSZ, (int)(WSZ / 4));
    round_kernel<<<(int)(WSZ / 4 + 255) / 256, 256>>>(W_ev, wr + 4 * WSZ, (int)(WSZ / 4));

    // ---- projections (NT, +bias, outputs rounded for chaining)
    mma_gemm<false><<<dim3(8, 128, 1), blk, SMEM_SZ>>>(orr, wr + 0 * WSZ, b_q,  q,   EMB_, EMB_, EMB_, PROJ_, 1.0f, 1, 0, 0, 0);
    mma_gemm<false><<<dim3(8,  64, 1), blk, SMEM_SZ>>>(srr, wr + 1 * WSZ, b_sk, sk,  EMB_, EMB_, EMB_, PROJ_, 1.0f, 1, 0, 0, 0);
    mma_gemm<true ><<<dim3(8,  64, 1), blk, SMEM_SZ>>>(srr, wr + 2 * WSZ, b_sv, vt,  EMB_, EMB_, EMB_, PROJ_, 1.0f, 1, 0, 0, 0);
    mma_gemm<false><<<dim3(8,  64, 1), blk, SMEM_SZ>>>(crr, wr + 3 * WSZ, b_ek, ek,  EMB_, EMB_, EMB_, PROJ_, 1.0f, 1, 0, 0, 0);
    mma_gemm<true ><<<dim3(8,  64, 1), blk, SMEM_SZ>>>(crr, wr + 4 * WSZ, b_ev, evt, EMB_, EMB_, EMB_, PROJ_, 1.0f, 1, 0, 0, 0);

    // ---- attention 1: S = scale*Q K^T ; softmax (rounds) ; O1 = S V
    mma_gemm<false><<<dim3(8, 16, BB), blk, SMEM_SZ>>>(q, sk, nullptr, S, PROJ_, PROJ_, PROJ_, SKV, scale, 0, ZP, ZV, ZS);
    softmax_kernel<<<BB * SQ, dim3(256)>>>(S);
    mma_gemm<false><<<dim3(8, 16, BB), blk, SMEM_SZ>>>(S, vt, nullptr, O1, SKV, SKV, SKV, PROJ_, 1.0f, 0, ZS, ZV, ZP);

    // ---- attention 2
    mma_gemm<false><<<dim3(8, 16, BB), blk, SMEM_SZ>>>(q, ek, nullptr, S, PROJ_, PROJ_, PROJ_, SKV, scale, 0, ZP, ZV, ZS);
    softmax_kernel<<<BB * SQ, dim3(256)>>>(S);
    mma_gemm<false><<<dim3(8, 16, BB), blk, SMEM_SZ>>>(S, evt, nullptr, O2, SKV, SKV, SKV, PROJ_, 1.0f, 0, ZS, ZV, ZP);

    // ---- residual + layernorm (original obj for residual)
    ln_kernel<<<BB * SQ, dim3(256)>>>(obj, O1, ln_g, ln_b);
    ln_kernel<<<BB * SQ, dim3(256)>>>(obj, O2, ln_g, ln_b);
}